// round 12
// baseline (speedup 1.0000x reference)
#include <cuda_runtime.h>

// Problem dims
#define B  64
#define L  1024
#define D  64
#define H  512
#define LN_EPS 1e-5f

// Partitioning: 8 batch-groups x 16 j-slices = 128 CTAs
#define GB 8     // batch groups
#define GJ 16    // hidden-column slices
#define BC 8     // batches per CTA   (B / GB)
#define JC 32    // j columns per CTA (H / GJ)
#define KG 16    // k-groups (warps; each owns 32 k-columns)
#define NT 512   // threads per CTA = JC * KG

// SMEM: Whh [3][128 k4][JC] float4  +  h_s [BC][H] float  +  red4 [BC][4][JC] float4
#define WHH_F4     (3 * 128 * JC)                 // 12288 float4 = 196608 B
#define RED4_N     (BC * 4 * JC)                  // 1024 float4  = 16384 B
#define SMEM_BYTES (WHH_F4 * 16 + BC * H * 4 + RED4_N * 16)   // 229376 B

typedef unsigned long long ull;

// Global scratch (static — no allocations allowed)
__device__ float g_h[2][B * H];   // ping-pong hidden state
__device__ int   g_cnt[GB];       // per-group monotonic release counters (8/CTA/step)
__device__ int   g_done[GB];      // exit counters (for reset)

// ---------------- packed f32x2 helpers ----------------
__device__ __forceinline__ void ffma2(ull& acc, ull a, ull b) {
    asm("fma.rn.f32x2 %0, %1, %2, %0;" : "+l"(acc) : "l"(a), "l"(b));
}
__device__ __forceinline__ ull add2(ull a, ull b) {
    ull r;
    asm("add.rn.f32x2 %0, %1, %2;" : "=l"(r) : "l"(a), "l"(b));
    return r;
}
__device__ __forceinline__ ull pk2f(float lo, float hi) {
    ull r;
    asm("mov.b64 %0, {%1, %2};" : "=l"(r) : "f"(lo), "f"(hi));
    return r;
}
__device__ __forceinline__ float upk_sum(ull v) {
    float lo, hi;
    asm("mov.b64 {%0, %1}, %2;" : "=f"(lo), "=f"(hi) : "l"(v));
    return lo + hi;
}

// ---------------- persistent recurrent kernel ----------------
__global__ void __launch_bounds__(NT, 1)
gru_kernel(const float* __restrict__ x,     // (B, L, D)
           const float* __restrict__ h0,    // (1, B, H)
           const float* __restrict__ W_ih,  // (3H, D)
           const float* __restrict__ W_hh,  // (3H, H)
           const float* __restrict__ b_ih,  // (3H)
           const float* __restrict__ b_hh,  // (3H)
           float* __restrict__ out_hseq,    // (B, L, H) — raw h, LN'd later in place
           float* __restrict__ out_hN)      // (1, B, H)
{
    extern __shared__ float4 smem[];
    float4* Whh_s = smem;                              // [3][128][JC] float4
    float*  h_s   = (float*)(smem + WHH_F4);           // [BC][H]
    float4* red4  = (float4*)(h_s + BC * H);           // [BC][4 slots][JC]: (r,z,hn,in)

    const int tid = threadIdx.x;
    const int j   = tid & 31;        // lane = hidden column within slice
    const int kg  = tid >> 5;        // warp id = k-group (0..15), 32 k each
    const int grp = blockIdx.x / GJ; // batch group
    const int slc = blockIdx.x % GJ; // j slice
    const int jg  = slc * JC + j;    // global hidden column
    const int bg0 = grp * BC;        // first global batch
    const int slot = kg & 3;
    const int phs  = kg >> 2;

    // ---- load W_hh slice into SMEM (once): 96 rows, 16 warps ----
    for (int rbase = 0; rbase < 96; rbase += 16) {
        int r  = rbase + kg;
        int g  = r >> 5;
        int jr = r & 31;
        const float4* src = (const float4*)(W_hh + ((size_t)(g * H + slc * JC + jr)) * H);
        #pragma unroll
        for (int c = 0; c < 4; c++) {
            int k4 = j + c * 32;
            Whh_s[(g * 128 + k4) * JC + jr] = src[k4];
        }
    }

    // ---- W_ih slice into registers: 4 floats of D per warp ----
    ull wih[3][2];
    #pragma unroll
    for (int g = 0; g < 3; g++) {
        const ull* src = (const ull*)(W_ih + (size_t)(g * H + jg) * D) + kg * 2;
        wih[g][0] = src[0];
        wih[g][1] = src[1];
    }

    // ---- biases for finalize (this thread's j column) ----
    const float bsr  = b_ih[jg]         + b_hh[jg];
    const float bsz  = b_ih[H + jg]     + b_hh[H + jg];
    const float bin_ = b_ih[2 * H + jg];
    const float bhn  = b_hh[2 * H + jg];

    // ---- stage initial h; h_old register for finalize threads ----
    {
        const float4* src = (const float4*)(h0 + (size_t)bg0 * H);
        float4* dst = (float4*)h_s;
        dst[tid]      = src[tid];
        dst[tid + NT] = src[tid + NT];
    }
    float h_old = (kg < 8) ? h0[(size_t)(bg0 + kg) * H + jg] : 0.f;

    // ---- accumulators; gi(t) computed directly into ar/az/an_ ----
    ull ar[BC], az[BC], an_[BC], ahn[BC];
    #define COMPUTE_GI(tt) do {                                                  \
        _Pragma("unroll")                                                        \
        for (int b = 0; b < BC; b++) {                                           \
            const ull* xp = (const ull*)(x + ((size_t)(bg0 + b) * L + (tt)) * D) \
                            + kg * 2;                                            \
            ull x0 = xp[0], x1 = xp[1];                                          \
            ar[b] = 0; az[b] = 0; an_[b] = 0;                                    \
            ffma2(ar[b],  wih[0][0], x0); ffma2(ar[b],  wih[0][1], x1);          \
            ffma2(az[b],  wih[1][0], x0); ffma2(az[b],  wih[1][1], x1);          \
            ffma2(an_[b], wih[2][0], x0); ffma2(an_[b], wih[2][1], x1);          \
        }                                                                        \
    } while (0)
    COMPUTE_GI(0);

    __syncthreads();

    for (int t = 0; t < L; t++) {
        // ---- recurrent GEMM over this warp's 32-col k-slab (acc pre-seeded with gi) ----
        #pragma unroll
        for (int b = 0; b < BC; b++) ahn[b] = 0;

        const int kb = kg * 8;
        #pragma unroll
        for (int k4m = 0; k4m < 8; k4m++) {
            const int k4 = kb + k4m;
            const ulonglong2 wr = *(const ulonglong2*)&Whh_s[(0 * 128 + k4) * JC + j];
            const ulonglong2 wz = *(const ulonglong2*)&Whh_s[(1 * 128 + k4) * JC + j];
            const ulonglong2 wn = *(const ulonglong2*)&Whh_s[(2 * 128 + k4) * JC + j];
            #pragma unroll
            for (int b = 0; b < BC; b++) {
                const ulonglong2 hv = *(const ulonglong2*)&h_s[b * H + k4 * 4];
                ffma2(ar[b],  wr.x, hv.x);  ffma2(ar[b],  wr.y, hv.y);
                ffma2(az[b],  wz.x, hv.x);  ffma2(az[b],  wz.y, hv.y);
                ffma2(ahn[b], wn.x, hv.x);  ffma2(ahn[b], wn.y, hv.y);
            }
        }

        // ---- 16-way cross-kg reduction: packed float4 channels, named-barrier chain ----
        // red4[(b*4+slot)*JC + j] = (r, z, hn, in); chain phs3 -> phs2 -> phs1 -> phs0
        if (phs == 3) {
            #pragma unroll
            for (int b = 0; b < BC; b++) {
                ulonglong2 v;
                v.x = pk2f(upk_sum(ar[b]),  upk_sum(az[b]));
                v.y = pk2f(upk_sum(ahn[b]), upk_sum(an_[b]));
                *(ulonglong2*)&red4[(b * 4 + slot) * JC + j] = v;
            }
            asm volatile("bar.arrive 1, 256;" ::: "memory");
            if (t + 1 < L) COMPUTE_GI(t + 1);
        } else if (phs == 2) {
            asm volatile("bar.sync 1, 256;" ::: "memory");
            #pragma unroll
            for (int b = 0; b < BC; b++) {
                ulonglong2* p = (ulonglong2*)&red4[(b * 4 + slot) * JC + j];
                ulonglong2 v = *p;
                v.x = add2(v.x, pk2f(upk_sum(ar[b]),  upk_sum(az[b])));
                v.y = add2(v.y, pk2f(upk_sum(ahn[b]), upk_sum(an_[b])));
                *p = v;
            }
            asm volatile("bar.arrive 2, 256;" ::: "memory");
            if (t + 1 < L) COMPUTE_GI(t + 1);
        } else if (phs == 1) {
            asm volatile("bar.sync 2, 256;" ::: "memory");
            #pragma unroll
            for (int b = 0; b < BC; b++) {
                ulonglong2* p = (ulonglong2*)&red4[(b * 4 + slot) * JC + j];
                ulonglong2 v = *p;
                v.x = add2(v.x, pk2f(upk_sum(ar[b]),  upk_sum(az[b])));
                v.y = add2(v.y, pk2f(upk_sum(ahn[b]), upk_sum(an_[b])));
                *p = v;
            }
            asm volatile("bar.arrive 3, 256;" ::: "memory");
            asm volatile("bar.sync 4, 256;" ::: "memory");
        } else { // phs == 0
            asm volatile("bar.sync 3, 256;" ::: "memory");
            #pragma unroll
            for (int b = 0; b < BC; b++) {
                ulonglong2* p = (ulonglong2*)&red4[(b * 4 + slot) * JC + j];
                ulonglong2 v = *p;
                v.x = add2(v.x, pk2f(upk_sum(ar[b]),  upk_sum(az[b])));
                v.y = add2(v.y, pk2f(upk_sum(ahn[b]), upk_sum(an_[b])));
                *p = v;
            }
            asm volatile("bar.sync 4, 256;" ::: "memory");
        }

        // ---- finalize: warps 0-7 (phs 0,1), one (b=kg, j=lane) pair per thread ----
        if (kg < 8) {
            const int b = kg;
            float4 v0 = red4[(b * 4 + 0) * JC + j];
            float4 v1 = red4[(b * 4 + 1) * JC + j];
            float4 v2 = red4[(b * 4 + 2) * JC + j];
            float4 v3 = red4[(b * 4 + 3) * JC + j];
            float sr  = (v0.x + v1.x) + (v2.x + v3.x);
            float sz  = (v0.y + v1.y) + (v2.y + v3.y);
            float shn = (v0.z + v1.z) + (v2.z + v3.z);
            float sn  = (v0.w + v1.w) + (v2.w + v3.w);

            float er = __expf(-(sr + bsr));
            float r  = __fdividef(1.f, 1.f + er);
            float ez = __expf(-(sz + bsz));
            float z  = __fdividef(1.f, 1.f + ez);
            float ta = sn + bin_ + r * (shn + bhn);
            ta = fminf(fmaxf(ta, -20.f), 20.f);
            float en = __expf(-2.f * ta);
            float n  = __fdividef(1.f - en, 1.f + en);   // tanh(ta)
            float hnew = fmaf(z, h_old - n, n);          // (1-z)n + z*h
            h_old = hnew;

            const int bglob = bg0 + b;
            g_h[t & 1][(size_t)bglob * H + jg] = hnew;
            out_hseq[((size_t)bglob * L + t) * H + jg] = hnew;
            if (t == L - 1) out_hN[(size_t)bglob * H + jg] = hnew;

            // per-warp release: this warp's g_h row is done
            __syncwarp();
            if (j == 0 && t + 1 < L) {
                asm volatile("red.release.gpu.global.add.u32 [%0], 1;"
                             :: "l"(&g_cnt[grp]) : "memory");
            }
            if (t + 1 < L) COMPUTE_GI(t + 1);
        }

        if (t + 1 < L) {
            if (tid == 0) {
                const int target = 8 * GJ * (t + 1);     // 8 releases per CTA per step
                int c;
                do {
                    asm volatile("ld.acquire.gpu.global.b32 %0, [%1];"
                                 : "=r"(c) : "l"(&g_cnt[grp]) : "memory");
                } while (c < target);
            }
            __syncthreads();   // flag observed; red4 + h_s safe to overwrite

            // warp-local restage: only this warp's 32-column k-slab (1 KB)
            {
                const float* src = g_h[t & 1] + (size_t)bg0 * H + 32 * kg;
                float* dst = h_s + 32 * kg;
                #pragma unroll
                for (int i = 0; i < 2; i++) {
                    int idx = i * 32 + j;          // 0..63 float4s in slab
                    int b = idx >> 3, c4 = idx & 7;
                    float4 val = *(const float4*)(src + (size_t)b * H + c4 * 4);
                    *(float4*)(dst + b * H + c4 * 4) = val;
                }
                __syncwarp();
            }
        }
    }

    // ---- exit protocol: reset counters for next graph replay ----
    if (tid == 0) {
        asm volatile("red.release.gpu.global.add.u32 [%0], 1;"
                     :: "l"(&g_done[grp]) : "memory");
        if (slc == 0) {
            int c;
            do {
                asm volatile("ld.acquire.gpu.global.b32 %0, [%1];"
                             : "=r"(c) : "l"(&g_done[grp]) : "memory");
            } while (c < GJ);
            g_cnt[grp]  = 0;
            g_done[grp] = 0;
        }
    }
}

// ---------------- LayerNorm (in place) + prediction GEMM, 4 rows/block ----------------
#define RPB 4
__global__ void __launch_bounds__(128)
ln_pred_kernel(const float* __restrict__ gamma, const float* __restrict__ beta,
               const float* __restrict__ Wp,    const float* __restrict__ bp,
               float* __restrict__ hseq,        float* __restrict__ xhat)
{
    __shared__ float sh[RPB][H];    // 8 KB

    const int row0 = blockIdx.x * RPB;
    const int tid  = threadIdx.x;
    const int w    = tid >> 5;      // warp = row for LN, jo-group for GEMM
    const int l    = tid & 31;

    // ---- LN: warp w normalizes row row0+w ----
    float* hp = hseq + (size_t)(row0 + w) * H;
    float4 v[4];
    float s = 0.f, q = 0.f;
    #pragma unroll
    for (int i = 0; i < 4; i++) {
        v[i] = ((const float4*)hp)[l + 32 * i];
        s += v[i].x + v[i].y + v[i].z + v[i].w;
        q += v[i].x * v[i].x + v[i].y * v[i].y + v[i].z * v[i].z + v[i].w * v[i].w;
    }
    #pragma unroll
    for (int o = 16; o; o >>= 1) {
        s += __shfl_xor_sync(0xffffffffu, s, o);
        q += __shfl_xor_sync(0xffffffffu, q, o);
    }
    const float mu = s * (1.f / H);
    const float rs = rsqrtf(q * (1.f / H) - mu * mu + LN_EPS);

    #pragma unroll
    for (int i = 0; i < 4; i++) {
        float4 g4 = ((const float4*)gamma)[l + 32 * i];
        float4 b4 = ((const float4*)beta)[l + 32 * i];
        float4 o;
        o.x = (v[i].x - mu) * rs * g4.x + b4.x;
        o.y = (v[i].y - mu) * rs * g4.y + b4.y;
        o.z = (v[i].z - mu) * rs * g4.z + b4.z;
        o.w = (v[i].w - mu) * rs * g4.w + b4.w;
        ((float4*)hp)[l + 32 * i] = o;              // in-place normalized
        ((float4*)&sh[w][0])[l + 32 * i] = o;
    }
    __syncthreads();

    // ---- all 4 rows' k-chunk into registers (reused across 16 jo) ----
    float4 hreg[RPB][4];
    #pragma unroll
    for (int r = 0; r < RPB; r++)
        #pragma unroll
        for (int i = 0; i < 4; i++)
            hreg[r][i] = ((const float4*)&sh[r][0])[l + 32 * i];

    // ---- GEMM: warp w computes jo = 16w .. 16w+15 for all 4 rows ----
    #pragma unroll 4
    for (int jj = 0; jj < 16; jj++) {
        const int jo = w * 16 + jj;
        const float4* wp4 = (const float4*)(Wp + (size_t)jo * H);
        float acc[RPB] = {0.f, 0.f, 0.f, 0.f};
        #pragma unroll
        for (int i = 0; i < 4; i++) {
            float4 wv = wp4[l + 32 * i];
            #pragma unroll
            for (int r = 0; r < RPB; r++) {
                acc[r] += wv.x * hreg[r][i].x + wv.y * hreg[r][i].y
                        + wv.z * hreg[r][i].z + wv.w * hreg[r][i].w;
            }
        }
        #pragma unroll
        for (int o = 16; o; o >>= 1)
            #pragma unroll
            for (int r = 0; r < RPB; r++)
                acc[r] += __shfl_xor_sync(0xffffffffu, acc[r], o);
        if (l == 0) {
            const float bj = bp[jo];
            #pragma unroll
            for (int r = 0; r < RPB; r++)
                xhat[(size_t)(row0 + r) * D + jo] = acc[r] + bj;
        }
    }
}

extern "C" void kernel_launch(void* const* d_in, const int* in_sizes, int n_in,
                              void* d_out, int out_size)
{
    const float* x      = (const float*)d_in[0];
    const float* h0     = (const float*)d_in[1];
    const float* W_ih   = (const float*)d_in[2];
    const float* W_hh   = (const float*)d_in[3];
    const float* b_ih   = (const float*)d_in[4];
    const float* b_hh   = (const float*)d_in[5];
    const float* gamma  = (const float*)d_in[6];
    const float* beta   = (const float*)d_in[7];
    const float* W_pred = (const float*)d_in[8];
    const float* b_pred = (const float*)d_in[9];

    float* out      = (float*)d_out;
    float* out_hseq = out;                                   // (B, L, H)
    float* out_hN   = out + (size_t)B * L * H;               // (1, B, H)
    float* out_xhat = out_hN + (size_t)B * H;                // (B, L, D)

    cudaFuncSetAttribute(gru_kernel, cudaFuncAttributeMaxDynamicSharedMemorySize,
                         SMEM_BYTES);

    gru_kernel<<<GB * GJ, NT, SMEM_BYTES>>>(x, h0, W_ih, W_hh, b_ih, b_hh,
                                            out_hseq, out_hN);
    ln_pred_kernel<<<(B * L) / RPB, 128>>>(gamma, beta, W_pred, b_pred,
                                           out_hseq, out_xhat);
}

// round 13
// speedup vs baseline: 1.5391x; 1.5391x over previous
#include <cuda_runtime.h>

// Problem dims
#define B  64
#define L  1024
#define D  64
#define H  512
#define LN_EPS 1e-5f

// Partitioning: 8 batch-groups x 16 j-slices = 128 CTAs
#define GB 8     // batch groups
#define GJ 16    // hidden-column slices
#define BC 8     // batches per CTA   (B / GB)
#define JC 32    // j columns per CTA (H / GJ)
#define KG 16    // k-groups (warps; each owns 32 k-columns)
#define NT 512   // threads per CTA = JC * KG

// SMEM: Whh [3][128 k4][JC] float4  +  h_s [BC][H] float  +  red4 [BC][4][JC] float4
#define WHH_F4     (3 * 128 * JC)                 // 12288 float4 = 196608 B
#define RED4_N     (BC * 4 * JC)                  // 1024 float4  = 16384 B
#define SMEM_BYTES (WHH_F4 * 16 + BC * H * 4 + RED4_N * 16)   // 229376 B

typedef unsigned long long ull;

// Global scratch (static — no allocations allowed)
__device__ float g_h[2][B * H];   // ping-pong hidden state
__device__ int   g_cnt[GB];       // per-group monotonic release counters (8/CTA/step)
__device__ int   g_done[GB];      // exit counters (for reset)

// ---------------- packed f32x2 helpers ----------------
__device__ __forceinline__ void ffma2(ull& acc, ull a, ull b) {
    asm("fma.rn.f32x2 %0, %1, %2, %0;" : "+l"(acc) : "l"(a), "l"(b));
}
__device__ __forceinline__ ull add2(ull a, ull b) {
    ull r;
    asm("add.rn.f32x2 %0, %1, %2;" : "=l"(r) : "l"(a), "l"(b));
    return r;
}
__device__ __forceinline__ ull pk2f(float lo, float hi) {
    ull r;
    asm("mov.b64 %0, {%1, %2};" : "=l"(r) : "f"(lo), "f"(hi));
    return r;
}
__device__ __forceinline__ float upk_sum(ull v) {
    float lo, hi;
    asm("mov.b64 {%0, %1}, %2;" : "=f"(lo), "=f"(hi) : "l"(v));
    return lo + hi;
}

// ---------------- persistent recurrent kernel ----------------
__global__ void __launch_bounds__(NT, 1)
gru_kernel(const float* __restrict__ x,     // (B, L, D)
           const float* __restrict__ h0,    // (1, B, H)
           const float* __restrict__ W_ih,  // (3H, D)
           const float* __restrict__ W_hh,  // (3H, H)
           const float* __restrict__ b_ih,  // (3H)
           const float* __restrict__ b_hh,  // (3H)
           float* __restrict__ out_hseq,    // (B, L, H) — raw h, LN'd later in place
           float* __restrict__ out_hN)      // (1, B, H)
{
    extern __shared__ float4 smem[];
    float4* Whh_s = smem;                              // [3][128][JC] float4
    float*  h_s   = (float*)(smem + WHH_F4);           // [BC][H]
    float4* red4  = (float4*)(h_s + BC * H);           // [BC][4 slots][JC]: (r,z,hn,in)

    const int tid = threadIdx.x;
    const int j   = tid & 31;        // lane = hidden column within slice
    const int kg  = tid >> 5;        // warp id = k-group (0..15), 32 k each
    const int grp = blockIdx.x / GJ; // batch group
    const int slc = blockIdx.x % GJ; // j slice
    const int jg  = slc * JC + j;    // global hidden column
    const int bg0 = grp * BC;        // first global batch
    const int slot = kg & 3;
    const int phs  = kg >> 2;

    // ---- load W_hh slice into SMEM (once): 96 rows, 16 warps ----
    for (int rbase = 0; rbase < 96; rbase += 16) {
        int r  = rbase + kg;
        int g  = r >> 5;
        int jr = r & 31;
        const float4* src = (const float4*)(W_hh + ((size_t)(g * H + slc * JC + jr)) * H);
        #pragma unroll
        for (int c = 0; c < 4; c++) {
            int k4 = j + c * 32;
            Whh_s[(g * 128 + k4) * JC + jr] = src[k4];
        }
    }

    // ---- W_ih slice into registers: 4 floats of D per warp ----
    ull wih[3][2];
    #pragma unroll
    for (int g = 0; g < 3; g++) {
        const ull* src = (const ull*)(W_ih + (size_t)(g * H + jg) * D) + kg * 2;
        wih[g][0] = src[0];
        wih[g][1] = src[1];
    }

    // ---- biases for finalize (this thread's j column) ----
    const float bsr  = b_ih[jg]         + b_hh[jg];
    const float bsz  = b_ih[H + jg]     + b_hh[H + jg];
    const float bin_ = b_ih[2 * H + jg];
    const float bhn  = b_hh[2 * H + jg];

    // ---- stage initial h; h_old register for finalize threads ----
    {
        const float4* src = (const float4*)(h0 + (size_t)bg0 * H);
        float4* dst = (float4*)h_s;
        dst[tid]      = src[tid];
        dst[tid + NT] = src[tid + NT];
    }
    float h_old = (kg < 8) ? h0[(size_t)(bg0 + kg) * H + jg] : 0.f;

    // ---- accumulators; gi(t) computed directly into ar/az/an_ ----
    ull ar[BC], az[BC], an_[BC], ahn[BC];
    #define COMPUTE_GI(tt) do {                                                  \
        _Pragma("unroll")                                                        \
        for (int b = 0; b < BC; b++) {                                           \
            const ull* xp = (const ull*)(x + ((size_t)(bg0 + b) * L + (tt)) * D) \
                            + kg * 2;                                            \
            ull x0 = xp[0], x1 = xp[1];                                          \
            ar[b] = 0; az[b] = 0; an_[b] = 0;                                    \
            ffma2(ar[b],  wih[0][0], x0); ffma2(ar[b],  wih[0][1], x1);          \
            ffma2(az[b],  wih[1][0], x0); ffma2(az[b],  wih[1][1], x1);          \
            ffma2(an_[b], wih[2][0], x0); ffma2(an_[b], wih[2][1], x1);          \
        }                                                                        \
    } while (0)
    COMPUTE_GI(0);

    __syncthreads();

    for (int t = 0; t < L; t++) {
        // ---- recurrent GEMM over this warp's 32-col k-slab (acc pre-seeded with gi) ----
        #pragma unroll
        for (int b = 0; b < BC; b++) ahn[b] = 0;

        const int kb = kg * 8;
        #pragma unroll
        for (int k4m = 0; k4m < 8; k4m++) {
            const int k4 = kb + k4m;
            const ulonglong2 wr = *(const ulonglong2*)&Whh_s[(0 * 128 + k4) * JC + j];
            const ulonglong2 wz = *(const ulonglong2*)&Whh_s[(1 * 128 + k4) * JC + j];
            const ulonglong2 wn = *(const ulonglong2*)&Whh_s[(2 * 128 + k4) * JC + j];
            #pragma unroll
            for (int b = 0; b < BC; b++) {
                const ulonglong2 hv = *(const ulonglong2*)&h_s[b * H + k4 * 4];
                ffma2(ar[b],  wr.x, hv.x);  ffma2(ar[b],  wr.y, hv.y);
                ffma2(az[b],  wz.x, hv.x);  ffma2(az[b],  wz.y, hv.y);
                ffma2(ahn[b], wn.x, hv.x);  ffma2(ahn[b], wn.y, hv.y);
            }
        }

        // ---- 16-way cross-kg reduction: packed float4 channels, named-barrier chain ----
        // red4[(b*4+slot)*JC + j] = (r, z, hn, in); chain phs3 -> phs2 -> phs1 -> phs0
        if (phs == 3) {
            #pragma unroll
            for (int b = 0; b < BC; b++) {
                ulonglong2 v;
                v.x = pk2f(upk_sum(ar[b]),  upk_sum(az[b]));
                v.y = pk2f(upk_sum(ahn[b]), upk_sum(an_[b]));
                *(ulonglong2*)&red4[(b * 4 + slot) * JC + j] = v;
            }
            asm volatile("bar.arrive 1, 256;" ::: "memory");
            if (t + 1 < L) COMPUTE_GI(t + 1);
        } else if (phs == 2) {
            asm volatile("bar.sync 1, 256;" ::: "memory");
            #pragma unroll
            for (int b = 0; b < BC; b++) {
                ulonglong2* p = (ulonglong2*)&red4[(b * 4 + slot) * JC + j];
                ulonglong2 v = *p;
                v.x = add2(v.x, pk2f(upk_sum(ar[b]),  upk_sum(az[b])));
                v.y = add2(v.y, pk2f(upk_sum(ahn[b]), upk_sum(an_[b])));
                *p = v;
            }
            asm volatile("bar.arrive 2, 256;" ::: "memory");
            if (t + 1 < L) COMPUTE_GI(t + 1);
        } else if (phs == 1) {
            asm volatile("bar.sync 2, 256;" ::: "memory");
            #pragma unroll
            for (int b = 0; b < BC; b++) {
                ulonglong2* p = (ulonglong2*)&red4[(b * 4 + slot) * JC + j];
                ulonglong2 v = *p;
                v.x = add2(v.x, pk2f(upk_sum(ar[b]),  upk_sum(az[b])));
                v.y = add2(v.y, pk2f(upk_sum(ahn[b]), upk_sum(an_[b])));
                *p = v;
            }
            asm volatile("bar.arrive 3, 256;" ::: "memory");
            asm volatile("bar.sync 4, 256;" ::: "memory");
        } else { // phs == 0
            asm volatile("bar.sync 3, 256;" ::: "memory");
            #pragma unroll
            for (int b = 0; b < BC; b++) {
                ulonglong2* p = (ulonglong2*)&red4[(b * 4 + slot) * JC + j];
                ulonglong2 v = *p;
                v.x = add2(v.x, pk2f(upk_sum(ar[b]),  upk_sum(az[b])));
                v.y = add2(v.y, pk2f(upk_sum(ahn[b]), upk_sum(an_[b])));
                *p = v;
            }
            asm volatile("bar.sync 4, 256;" ::: "memory");
        }

        // ---- finalize: warps 0-7 (phs 0,1), one (b=kg, j=lane) pair per thread ----
        if (kg < 8) {
            const int b = kg;
            float4 v0 = red4[(b * 4 + 0) * JC + j];
            float4 v1 = red4[(b * 4 + 1) * JC + j];
            float4 v2 = red4[(b * 4 + 2) * JC + j];
            float4 v3 = red4[(b * 4 + 3) * JC + j];
            float sr  = (v0.x + v1.x) + (v2.x + v3.x);
            float sz  = (v0.y + v1.y) + (v2.y + v3.y);
            float shn = (v0.z + v1.z) + (v2.z + v3.z);
            float sn  = (v0.w + v1.w) + (v2.w + v3.w);

            float er = __expf(-(sr + bsr));
            float r  = __fdividef(1.f, 1.f + er);
            float ez = __expf(-(sz + bsz));
            float z  = __fdividef(1.f, 1.f + ez);
            float ta = sn + bin_ + r * (shn + bhn);
            ta = fminf(fmaxf(ta, -20.f), 20.f);
            float en = __expf(-2.f * ta);
            float n  = __fdividef(1.f - en, 1.f + en);   // tanh(ta)
            float hnew = fmaf(z, h_old - n, n);          // (1-z)n + z*h
            h_old = hnew;

            const int bglob = bg0 + b;
            g_h[t & 1][(size_t)bglob * H + jg] = hnew;
            out_hseq[((size_t)bglob * L + t) * H + jg] = hnew;
            if (t == L - 1) out_hN[(size_t)bglob * H + jg] = hnew;

            // per-warp release: this warp's g_h row is done
            __syncwarp();
            if (j == 0 && t + 1 < L) {
                asm volatile("red.release.gpu.global.add.u32 [%0], 1;"
                             :: "l"(&g_cnt[grp]) : "memory");
            }
            if (t + 1 < L) COMPUTE_GI(t + 1);
        }

        if (t + 1 < L) {
            if (tid == 0) {
                const int target = 8 * GJ * (t + 1);     // 8 releases per CTA per step
                int c;
                do {
                    asm volatile("ld.acquire.gpu.global.b32 %0, [%1];"
                                 : "=r"(c) : "l"(&g_cnt[grp]) : "memory");
                } while (c < target);
            }
            __syncthreads();   // flag observed; red4 + h_s safe to overwrite

            // warp-local restage: only this warp's 32-column k-slab (1 KB)
            {
                const float* src = g_h[t & 1] + (size_t)bg0 * H + 32 * kg;
                float* dst = h_s + 32 * kg;
                #pragma unroll
                for (int i = 0; i < 2; i++) {
                    int idx = i * 32 + j;          // 0..63 float4s in slab
                    int b = idx >> 3, c4 = idx & 7;
                    float4 val = *(const float4*)(src + (size_t)b * H + c4 * 4);
                    *(float4*)(dst + b * H + c4 * 4) = val;
                }
                __syncwarp();
            }
        }
    }

    // ---- exit protocol: reset counters for next graph replay ----
    if (tid == 0) {
        asm volatile("red.release.gpu.global.add.u32 [%0], 1;"
                     :: "l"(&g_done[grp]) : "memory");
        if (slc == 0) {
            int c;
            do {
                asm volatile("ld.acquire.gpu.global.b32 %0, [%1];"
                             : "=r"(c) : "l"(&g_done[grp]) : "memory");
            } while (c < GJ);
            g_cnt[grp]  = 0;
            g_done[grp] = 0;
        }
    }
}

// ---------------- LayerNorm (in place) + prediction GEMM, 4 rows/block ----------------
#define RPB 4
__global__ void __launch_bounds__(128)
ln_pred_kernel(const float* __restrict__ gamma, const float* __restrict__ beta,
               const float* __restrict__ Wp,    const float* __restrict__ bp,
               float* __restrict__ hseq,        float* __restrict__ xhat)
{
    __shared__ float sh[RPB][H];    // 8 KB

    const int row0 = blockIdx.x * RPB;
    const int tid  = threadIdx.x;
    const int w    = tid >> 5;      // warp = row for LN, jo-group for GEMM
    const int l    = tid & 31;

    // ---- LN: warp w normalizes row row0+w ----
    float* hp = hseq + (size_t)(row0 + w) * H;
    float4 v[4];
    float s = 0.f, q = 0.f;
    #pragma unroll
    for (int i = 0; i < 4; i++) {
        v[i] = ((const float4*)hp)[l + 32 * i];
        s += v[i].x + v[i].y + v[i].z + v[i].w;
        q += v[i].x * v[i].x + v[i].y * v[i].y + v[i].z * v[i].z + v[i].w * v[i].w;
    }
    #pragma unroll
    for (int o = 16; o; o >>= 1) {
        s += __shfl_xor_sync(0xffffffffu, s, o);
        q += __shfl_xor_sync(0xffffffffu, q, o);
    }
    const float mu = s * (1.f / H);
    const float rs = rsqrtf(q * (1.f / H) - mu * mu + LN_EPS);

    #pragma unroll
    for (int i = 0; i < 4; i++) {
        float4 g4 = ((const float4*)gamma)[l + 32 * i];
        float4 b4 = ((const float4*)beta)[l + 32 * i];
        float4 o;
        o.x = (v[i].x - mu) * rs * g4.x + b4.x;
        o.y = (v[i].y - mu) * rs * g4.y + b4.y;
        o.z = (v[i].z - mu) * rs * g4.z + b4.z;
        o.w = (v[i].w - mu) * rs * g4.w + b4.w;
        ((float4*)hp)[l + 32 * i] = o;              // in-place normalized
        ((float4*)&sh[w][0])[l + 32 * i] = o;
    }
    __syncthreads();

    // ---- all 4 rows' k-chunk into registers (reused across 16 jo) ----
    float4 hreg[RPB][4];
    #pragma unroll
    for (int r = 0; r < RPB; r++)
        #pragma unroll
        for (int i = 0; i < 4; i++)
            hreg[r][i] = ((const float4*)&sh[r][0])[l + 32 * i];

    // ---- GEMM: warp w computes jo = 16w .. 16w+15 for all 4 rows ----
    #pragma unroll 4
    for (int jj = 0; jj < 16; jj++) {
        const int jo = w * 16 + jj;
        const float4* wp4 = (const float4*)(Wp + (size_t)jo * H);
        float acc[RPB] = {0.f, 0.f, 0.f, 0.f};
        #pragma unroll
        for (int i = 0; i < 4; i++) {
            float4 wv = wp4[l + 32 * i];
            #pragma unroll
            for (int r = 0; r < RPB; r++) {
                acc[r] += wv.x * hreg[r][i].x + wv.y * hreg[r][i].y
                        + wv.z * hreg[r][i].z + wv.w * hreg[r][i].w;
            }
        }
        #pragma unroll
        for (int o = 16; o; o >>= 1)
            #pragma unroll
            for (int r = 0; r < RPB; r++)
                acc[r] += __shfl_xor_sync(0xffffffffu, acc[r], o);
        if (l == 0) {
            const float bj = bp[jo];
            #pragma unroll
            for (int r = 0; r < RPB; r++)
                xhat[(size_t)(row0 + r) * D + jo] = acc[r] + bj;
        }
    }
}

extern "C" void kernel_launch(void* const* d_in, const int* in_sizes, int n_in,
                              void* d_out, int out_size)
{
    const float* x      = (const float*)d_in[0];
    const float* h0     = (const float*)d_in[1];
    const float* W_ih   = (const float*)d_in[2];
    const float* W_hh   = (const float*)d_in[3];
    const float* b_ih   = (const float*)d_in[4];
    const float* b_hh   = (const float*)d_in[5];
    const float* gamma  = (const float*)d_in[6];
    const float* beta   = (const float*)d_in[7];
    const float* W_pred = (const float*)d_in[8];
    const float* b_pred = (const float*)d_in[9];

    float* out      = (float*)d_out;
    float* out_hseq = out;                                   // (B, L, H)
    float* out_hN   = out + (size_t)B * L * H;               // (1, B, H)
    float* out_xhat = out_hN + (size_t)B * H;                // (B, L, D)

    cudaFuncSetAttribute(gru_kernel, cudaFuncAttributeMaxDynamicSharedMemorySize,
                         SMEM_BYTES);

    gru_kernel<<<GB * GJ, NT, SMEM_BYTES>>>(x, h0, W_ih, W_hh, b_ih, b_hh,
                                            out_hseq, out_hN);
    ln_pred_kernel<<<(B * L) / RPB, 128>>>(gamma, beta, W_pred, b_pred,
                                           out_hseq, out_xhat);
}

// round 16
// speedup vs baseline: 1.5668x; 1.0180x over previous
#include <cuda_runtime.h>
#include <cuda_bf16.h>
#include <cstdint>

#define B  64
#define L  1024
#define D  64
#define H  512
#define LN_EPS 1e-5f

// Partitioning: 4 batch-groups x 32 unit-slices = 128 CTAs
#define GB 4
#define GJ 32
#define BC 16    // batches per CTA
#define JC 16    // hidden units per CTA
#define NT 384   // 12 warps

// ---- SMEM layout (byte offsets) ----
// A-frags: [mt 0..2][ktt 0..35][lane 0..31] x 16B  (3*36*32*16 = 55296 B each)
#define OFF_AHI 0
#define OFF_ALO 55296
// B-frags: [ktt 0..35][nt 0..1][lane 0..31] x 8B   (36*2*32*8 = 18432 B each)
#define OFF_BHI 110592
#define OFF_BLO 129024
// D tiles: [mt 0..2][n 0..15][r 0..16] fp32 stride 17  (3*272*4 = 3264 B each)
#define OFF_DHI 147456
#define OFF_DLO 150720
// x-part of n-gate: [n][r] stride 17 (1088 B each)
#define OFF_DXH 153984
#define OFF_DXL 155072
#define SMEM_BYTES 156160

typedef unsigned long long ull;

__device__ float g_h[2][B * H];   // ping-pong hidden state (fp32)
__device__ int   g_cnt[GB];       // per-group monotonic release counters
__device__ int   g_done[GB];      // exit counters (reset for graph replay)

// ---------------- helpers ----------------
__device__ __forceinline__ uint32_t pkhi(float2 v) {
    __nv_bfloat162 h = __floats2bfloat162_rn(v.x, v.y);
    return *reinterpret_cast<uint32_t*>(&h);
}
__device__ __forceinline__ uint32_t pklo(float2 v) {
    float rx = v.x - __bfloat162float(__float2bfloat16_rn(v.x));
    float ry = v.y - __bfloat162float(__float2bfloat16_rn(v.y));
    __nv_bfloat162 h = __floats2bfloat162_rn(rx, ry);
    return *reinterpret_cast<uint32_t*>(&h);
}
__device__ __forceinline__ void mma4(float* d, uint4 A, uint2 Bv) {
    asm volatile("mma.sync.aligned.m16n8k16.row.col.f32.bf16.bf16.f32 "
        "{%0,%1,%2,%3}, {%4,%5,%6,%7}, {%8,%9}, {%0,%1,%2,%3};"
        : "+f"(d[0]), "+f"(d[1]), "+f"(d[2]), "+f"(d[3])
        : "r"(A.x), "r"(A.y), "r"(A.z), "r"(A.w), "r"(Bv.x), "r"(Bv.y));
}

// stage h (16 x 512 fp32 at src) into hi/lo B-fragments (k-tiles 0..31)
__device__ __forceinline__ void stage_h_frags(const float* src, char* smem, int tid) {
    for (int p = tid; p < 2048; p += NT) {
        const int lane = p & 31;
        const int nt   = (p >> 5) & 1;
        const int kt   = p >> 6;                  // 0..31
        const int n    = nt * 8 + (lane >> 2);
        const int k    = kt * 16 + ((lane & 3) << 1);
        const float* hp = src + (size_t)n * H + k;
        float2 va = *(const float2*)(hp);
        float2 vb = *(const float2*)(hp + 8);
        const size_t off = (size_t)((kt * 2 + nt) * 32 + lane) * 8;
        *(uint2*)(smem + OFF_BHI + off) = make_uint2(pkhi(va), pkhi(vb));
        *(uint2*)(smem + OFF_BLO + off) = make_uint2(pklo(va), pklo(vb));
    }
}

// stage x(t) (16 batches x 64) into hi/lo B-fragments (k-tiles 32..35)
// xb = x + (bg0*L + t)*D ; batch n offset = n*L*D
__device__ __forceinline__ void stage_x_frags(const float* xb, char* smem,
                                              int p0, int pstep) {
    for (int p = p0; p < 256; p += pstep) {
        const int lane = p & 31;
        const int nt   = (p >> 5) & 1;
        const int ktx  = p >> 6;                  // 0..3
        const int n    = nt * 8 + (lane >> 2);
        const int k    = ktx * 16 + ((lane & 3) << 1);
        const float* xp = xb + (size_t)n * L * D + k;
        float2 va = *(const float2*)(xp);
        float2 vb = *(const float2*)(xp + 8);
        const size_t off = (size_t)(((32 + ktx) * 2 + nt) * 32 + lane) * 8;
        *(uint2*)(smem + OFF_BHI + off) = make_uint2(pkhi(va), pkhi(vb));
        *(uint2*)(smem + OFF_BLO + off) = make_uint2(pklo(va), pklo(vb));
    }
}

// ---------------- persistent recurrent kernel (mma.sync) ----------------
__global__ void __launch_bounds__(NT, 1)
gru_kernel(const float* __restrict__ x,     const float* __restrict__ h0,
           const float* __restrict__ W_ih,  const float* __restrict__ W_hh,
           const float* __restrict__ b_ih,  const float* __restrict__ b_hh,
           float* __restrict__ out_hseq,    float* __restrict__ out_hN)
{
    extern __shared__ char smem[];
    float* DHI = (float*)(smem + OFF_DHI);
    float* DLO = (float*)(smem + OFF_DLO);
    float* DXH = (float*)(smem + OFF_DXH);
    float* DXL = (float*)(smem + OFF_DXL);

    const int tid  = threadIdx.x;
    const int w    = tid >> 5;
    const int lane = tid & 31;
    const int grp  = blockIdx.x / GJ;
    const int slc  = blockIdx.x % GJ;
    const int bg0  = grp * BC;

    // ---- stage A-fragments (once): Whh k-tiles 0..31, Wih k-tiles 32..35 ----
    for (int f = tid; f < 3456; f += NT) {
        const int ln  = f & 31;
        const int ktt = (f >> 5) % 36;
        const int mt  = f / 1152;                 // gate (0=r,1=z,2=n)
        const int r0  = ln >> 2;
        const int c0  = (ln & 3) * 2;
        const int rowA = slc * JC + r0;
        const float *pA, *pB;
        if (ktt < 32) {
            const int k = ktt * 16 + c0;
            pA = W_hh + ((size_t)(mt * H + rowA)) * H + k;
            pB = W_hh + ((size_t)(mt * H + rowA + 8)) * H + k;
        } else {
            const int k = (ktt - 32) * 16 + c0;
            pA = W_ih + ((size_t)(mt * H + rowA)) * D + k;
            pB = W_ih + ((size_t)(mt * H + rowA + 8)) * D + k;
        }
        float2 a0 = *(const float2*)pA, a1 = *(const float2*)(pA + 8);
        float2 b0 = *(const float2*)pB, b1 = *(const float2*)(pB + 8);
        // frag reg order: (r0,c0), (r0+8,c0), (r0,c0+8), (r0+8,c0+8)
        *(uint4*)(smem + OFF_AHI + (size_t)f * 16) =
            make_uint4(pkhi(a0), pkhi(b0), pkhi(a1), pkhi(b1));
        *(uint4*)(smem + OFF_ALO + (size_t)f * 16) =
            make_uint4(pklo(a0), pklo(b0), pklo(a1), pklo(b1));
    }

    // ---- finalize-thread state (tid < 256): (u, bb) ----
    const int u  = tid & 15;
    const int bb = (tid >> 4) & 15;
    const int jg = slc * JC + u;
    const float bsr  = b_ih[jg]         + b_hh[jg];
    const float bsz  = b_ih[H + jg]     + b_hh[H + jg];
    const float bin_ = b_ih[2 * H + jg];
    const float bhn  = b_hh[2 * H + jg];
    float h_old = (tid < 256) ? h0[(size_t)(bg0 + bb) * H + jg] : 0.f;

    // ---- prologue: B-frags for h(-1) = h0 and x(0) ----
    stage_h_frags(h0 + (size_t)bg0 * H, smem, tid);
    stage_x_frags(x + (size_t)bg0 * L * D, smem, tid, NT);
    __syncthreads();

    // job decode: warps 0-5 = hi-role, 6-11 = lo-role
    const int  wv = (w < 6) ? w : (w - 6);
    const int  mt = wv >> 1;
    const int  nt = wv & 1;
    const bool hiRole = (w < 6);
    const char* Ab = smem + (hiRole ? OFF_AHI : OFF_ALO)
                   + ((size_t)(mt * 1152) + lane) * 16;     // + ktt*512
    const char* Bh = smem + OFF_BHI + ((size_t)(nt * 32) + lane) * 8;  // + ktt*512
    const char* Bl = smem + OFF_BLO + ((size_t)(nt * 32) + lane) * 8;

    for (int t = 0; t < L; t++) {
        // ================= MMA phase =================
        if (hiRole) {
            float aH0[4] = {0,0,0,0}, aH1[4] = {0,0,0,0};
            float aL0[4] = {0,0,0,0}, aL1[4] = {0,0,0,0};
            float aXH[4] = {0,0,0,0}, aXL[4] = {0,0,0,0};
            #pragma unroll
            for (int k2 = 0; k2 < 16; k2++) {
                {
                    const int ktt = 2 * k2;
                    uint4 A = *(const uint4*)(Ab + (size_t)ktt * 512);
                    uint2 bh = *(const uint2*)(Bh + (size_t)ktt * 512);
                    uint2 bl = *(const uint2*)(Bl + (size_t)ktt * 512);
                    mma4(aH0, A, bh);
                    mma4(aL0, A, bl);
                }
                {
                    const int ktt = 2 * k2 + 1;
                    uint4 A = *(const uint4*)(Ab + (size_t)ktt * 512);
                    uint2 bh = *(const uint2*)(Bh + (size_t)ktt * 512);
                    uint2 bl = *(const uint2*)(Bl + (size_t)ktt * 512);
                    mma4(aH1, A, bh);
                    mma4(aL1, A, bl);
                }
            }
            #pragma unroll
            for (int q = 0; q < 4; q++) {
                const int ktt = 32 + q;
                uint4 A = *(const uint4*)(Ab + (size_t)ktt * 512);
                uint2 bh = *(const uint2*)(Bh + (size_t)ktt * 512);
                uint2 bl = *(const uint2*)(Bl + (size_t)ktt * 512);
                mma4(aXH, A, bh);
                mma4(aXL, A, bl);
            }
            const int n0 = nt * 8 + (lane & 3) * 2;
            const int r0 = lane >> 2;
            if (mt < 2) {
                #pragma unroll
                for (int i = 0; i < 4; i++)
                    aH0[i] = ((aH0[i] + aH1[i]) + (aL0[i] + aL1[i])) + (aXH[i] + aXL[i]);
                float* dst = DHI + mt * 272;
                dst[n0 * 17 + r0]           = aH0[0];
                dst[(n0 + 1) * 17 + r0]     = aH0[1];
                dst[n0 * 17 + r0 + 8]       = aH0[2];
                dst[(n0 + 1) * 17 + r0 + 8] = aH0[3];
            } else {
                #pragma unroll
                for (int i = 0; i < 4; i++) {
                    aH0[i] = (aH0[i] + aH1[i]) + (aL0[i] + aL1[i]);
                    aXH[i] = aXH[i] + aXL[i];
                }
                float* dst = DHI + 2 * 272;
                dst[n0 * 17 + r0]           = aH0[0];
                dst[(n0 + 1) * 17 + r0]     = aH0[1];
                dst[n0 * 17 + r0 + 8]       = aH0[2];
                dst[(n0 + 1) * 17 + r0 + 8] = aH0[3];
                DXH[n0 * 17 + r0]           = aXH[0];
                DXH[(n0 + 1) * 17 + r0]     = aXH[1];
                DXH[n0 * 17 + r0 + 8]       = aXH[2];
                DXH[(n0 + 1) * 17 + r0 + 8] = aXH[3];
            }
        } else {
            float a0[4] = {0,0,0,0}, a1[4] = {0,0,0,0}, aX[4] = {0,0,0,0};
            #pragma unroll
            for (int k2 = 0; k2 < 16; k2++) {
                {
                    const int ktt = 2 * k2;
                    uint4 A = *(const uint4*)(Ab + (size_t)ktt * 512);
                    uint2 bh = *(const uint2*)(Bh + (size_t)ktt * 512);
                    mma4(a0, A, bh);
                }
                {
                    const int ktt = 2 * k2 + 1;
                    uint4 A = *(const uint4*)(Ab + (size_t)ktt * 512);
                    uint2 bh = *(const uint2*)(Bh + (size_t)ktt * 512);
                    mma4(a1, A, bh);
                }
            }
            #pragma unroll
            for (int q = 0; q < 4; q++) {
                const int ktt = 32 + q;
                uint4 A = *(const uint4*)(Ab + (size_t)ktt * 512);
                uint2 bh = *(const uint2*)(Bh + (size_t)ktt * 512);
                mma4(aX, A, bh);
            }
            const int n0 = nt * 8 + (lane & 3) * 2;
            const int r0 = lane >> 2;
            if (mt < 2) {
                #pragma unroll
                for (int i = 0; i < 4; i++) a0[i] = (a0[i] + a1[i]) + aX[i];
                float* dst = DLO + mt * 272;
                dst[n0 * 17 + r0]           = a0[0];
                dst[(n0 + 1) * 17 + r0]     = a0[1];
                dst[n0 * 17 + r0 + 8]       = a0[2];
                dst[(n0 + 1) * 17 + r0 + 8] = a0[3];
            } else {
                #pragma unroll
                for (int i = 0; i < 4; i++) a0[i] = a0[i] + a1[i];
                float* dst = DLO + 2 * 272;
                dst[n0 * 17 + r0]           = a0[0];
                dst[(n0 + 1) * 17 + r0]     = a0[1];
                dst[n0 * 17 + r0 + 8]       = a0[2];
                dst[(n0 + 1) * 17 + r0 + 8] = a0[3];
                DXL[n0 * 17 + r0]           = aX[0];
                DXL[(n0 + 1) * 17 + r0]     = aX[1];
                DXL[n0 * 17 + r0 + 8]       = aX[2];
                DXL[(n0 + 1) * 17 + r0 + 8] = aX[3];
            }
        }
        __syncthreads();   // D tiles visible; all B-frag reads complete

        // ================= finalize (warps 0-7) | x-stage (warps 8-11) =====
        if (tid < 256) {
            const int idx = bb * 17 + u;
            float sr = DHI[idx]       + DLO[idx];
            float sz = DHI[272 + idx] + DLO[272 + idx];
            float hn = DHI[544 + idx] + DLO[544 + idx];
            float xn = DXH[idx]       + DXL[idx];

            float er = __expf(-(sr + bsr));
            float r  = __fdividef(1.f, 1.f + er);
            float ez = __expf(-(sz + bsz));
            float z  = __fdividef(1.f, 1.f + ez);
            float ta = xn + bin_ + r * (hn + bhn);
            ta = fminf(fmaxf(ta, -20.f), 20.f);
            float en = __expf(-2.f * ta);
            float n  = __fdividef(1.f - en, 1.f + en);
            float hnew = fmaf(z, h_old - n, n);
            h_old = hnew;

            const int bglob = bg0 + bb;
            g_h[t & 1][(size_t)bglob * H + jg] = hnew;
            out_hseq[((size_t)bglob * L + t) * H + jg] = hnew;
            if (t == L - 1) out_hN[(size_t)bglob * H + jg] = hnew;

            __syncwarp();
            if (lane == 0 && t + 1 < L) {
                asm volatile("red.release.gpu.global.add.u32 [%0], 1;"
                             :: "l"(&g_cnt[grp]) : "memory");
            }
        } else if (t + 1 < L) {
            // warps 8-11: stage x(t+1) fragments (k-tiles 32..35)
            stage_x_frags(x + ((size_t)bg0 * L + (t + 1)) * D, smem, tid - 256, 128);
        }

        // ================= exchange =================
        if (t + 1 < L) {
            if (tid == 0) {
                const int target = 8 * GJ * (t + 1);   // 8 releases/CTA/step
                int c;
                do {
                    asm volatile("ld.acquire.gpu.global.b32 %0, [%1];"
                                 : "=r"(c) : "l"(&g_cnt[grp]) : "memory");
                } while (c < target);
            }
            __syncthreads();
            stage_h_frags(g_h[t & 1] + (size_t)bg0 * H, smem, tid);
            __syncthreads();
        }
    }

    // ---- exit protocol: reset counters for next graph replay ----
    if (tid == 0) {
        asm volatile("red.release.gpu.global.add.u32 [%0], 1;"
                     :: "l"(&g_done[grp]) : "memory");
        if (slc == 0) {
            int c;
            do {
                asm volatile("ld.acquire.gpu.global.b32 %0, [%1];"
                             : "=r"(c) : "l"(&g_done[grp]) : "memory");
            } while (c < GJ);
            g_cnt[grp]  = 0;
            g_done[grp] = 0;
        }
    }
}

// ---------------- LayerNorm (in place) + prediction GEMM, 4 rows/block ----------------
#define RPB 4
__global__ void __launch_bounds__(128)
ln_pred_kernel(const float* __restrict__ gamma, const float* __restrict__ beta,
               const float* __restrict__ Wp,    const float* __restrict__ bp,
               float* __restrict__ hseq,        float* __restrict__ xhat)
{
    __shared__ float sh[RPB][H];
    const int row0 = blockIdx.x * RPB;
    const int tid  = threadIdx.x;
    const int w    = tid >> 5, l = tid & 31;

    float* hp = hseq + (size_t)(row0 + w) * H;
    float4 v[4];
    float s = 0.f, q = 0.f;
    #pragma unroll
    for (int i = 0; i < 4; i++) {
        v[i] = ((const float4*)hp)[l + 32 * i];
        s += v[i].x + v[i].y + v[i].z + v[i].w;
        q += v[i].x * v[i].x + v[i].y * v[i].y + v[i].z * v[i].z + v[i].w * v[i].w;
    }
    #pragma unroll
    for (int o = 16; o; o >>= 1) {
        s += __shfl_xor_sync(0xffffffffu, s, o);
        q += __shfl_xor_sync(0xffffffffu, q, o);
    }
    const float mu = s * (1.f / H);
    const float rs = rsqrtf(q * (1.f / H) - mu * mu + LN_EPS);

    #pragma unroll
    for (int i = 0; i < 4; i++) {
        float4 g4 = ((const float4*)gamma)[l + 32 * i];
        float4 b4 = ((const float4*)beta)[l + 32 * i];
        float4 o;
        o.x = (v[i].x - mu) * rs * g4.x + b4.x;
        o.y = (v[i].y - mu) * rs * g4.y + b4.y;
        o.z = (v[i].z - mu) * rs * g4.z + b4.z;
        o.w = (v[i].w - mu) * rs * g4.w + b4.w;
        ((float4*)hp)[l + 32 * i] = o;
        ((float4*)&sh[w][0])[l + 32 * i] = o;
    }
    __syncthreads();

    float4 hreg[RPB][4];
    #pragma unroll
    for (int r = 0; r < RPB; r++)
        #pragma unroll
        for (int i = 0; i < 4; i++)
            hreg[r][i] = ((const float4*)&sh[r][0])[l + 32 * i];

    #pragma unroll 4
    for (int jj = 0; jj < 16; jj++) {
        const int jo = w * 16 + jj;
        const float4* wp4 = (const float4*)(Wp + (size_t)jo * H);
        float acc[RPB] = {0.f, 0.f, 0.f, 0.f};
        #pragma unroll
        for (int i = 0; i < 4; i++) {
            float4 wv = wp4[l + 32 * i];
            #pragma unroll
            for (int r = 0; r < RPB; r++)
                acc[r] += wv.x * hreg[r][i].x + wv.y * hreg[r][i].y
                        + wv.z * hreg[r][i].z + wv.w * hreg[r][i].w;
        }
        #pragma unroll
        for (int o = 16; o; o >>= 1)
            #pragma unroll
            for (int r = 0; r < RPB; r++)
                acc[r] += __shfl_xor_sync(0xffffffffu, acc[r], o);
        if (l == 0) {
            const float bj = bp[jo];
            #pragma unroll
            for (int r = 0; r < RPB; r++)
                xhat[(size_t)(row0 + r) * D + jo] = acc[r] + bj;
        }
    }
}

extern "C" void kernel_launch(void* const* d_in, const int* in_sizes, int n_in,
                              void* d_out, int out_size)
{
    const float* x      = (const float*)d_in[0];
    const float* h0     = (const float*)d_in[1];
    const float* W_ih   = (const float*)d_in[2];
    const float* W_hh   = (const float*)d_in[3];
    const float* b_ih   = (const float*)d_in[4];
    const float* b_hh   = (const float*)d_in[5];
    const float* gamma  = (const float*)d_in[6];
    const float* beta   = (const float*)d_in[7];
    const float* W_pred = (const float*)d_in[8];
    const float* b_pred = (const float*)d_in[9];

    float* out      = (float*)d_out;
    float* out_hseq = out;                                   // (B, L, H)
    float* out_hN   = out + (size_t)B * L * H;               // (1, B, H)
    float* out_xhat = out_hN + (size_t)B * H;                // (B, L, D)

    cudaFuncSetAttribute(gru_kernel, cudaFuncAttributeMaxDynamicSharedMemorySize,
                         SMEM_BYTES);

    gru_kernel<<<GB * GJ, NT, SMEM_BYTES>>>(x, h0, W_ih, W_hh, b_ih, b_hh,
                                            out_hseq, out_hN);
    ln_pred_kernel<<<(B * L) / RPB, 128>>>(gamma, beta, W_pred, b_pred,
                                           out_hseq, out_xhat);
}